// round 1
// baseline (speedup 1.0000x reference)
#include <cuda_runtime.h>
#include <cstdint>
#include <math.h>

#define HIDDEN 2048
#define NHEADS 16
#define HDIM 128
#define FFDIM 5632
#define BATCHN 2
#define SEQ 2048
#define NTOK (BATCHN*SEQ)   // 4096

// ---------------- scratch (device globals: no allocation allowed) ----------------
__device__ float g_xnorm[NTOK*HIDDEN];
__device__ float g_q[NTOK*HIDDEN];
__device__ float g_k[NTOK*HIDDEN];
__device__ float g_v[NTOK*HIDDEN];
__device__ float g_attnout[NTOK*HIDDEN];
__device__ float g_h[NTOK*HIDDEN];
__device__ float g_ffn[NTOK*HIDDEN];
__device__ float g_scores[(size_t)BATCHN*NHEADS*SEQ*SEQ];   // 512 MB
__device__ float g_g1[(size_t)NTOK*FFDIM];
__device__ float g_g3[(size_t)NTOK*FFDIM];
// tf32-rounded weights
__device__ float g_wq[HIDDEN*HIDDEN];
__device__ float g_wk[HIDDEN*HIDDEN];
__device__ float g_wv[HIDDEN*HIDDEN];
__device__ float g_wo[HIDDEN*HIDDEN];
__device__ float g_w1[(size_t)HIDDEN*FFDIM];
__device__ float g_w3[(size_t)HIDDEN*FFDIM];
__device__ float g_w2[(size_t)FFDIM*HIDDEN];

// ---------------- helpers ----------------
__device__ __forceinline__ float rna_tf32(float x){
    unsigned r; asm("cvt.rna.tf32.f32 %0, %1;" : "=r"(r) : "f"(x));
    return __uint_as_float(r);
}
__device__ __forceinline__ unsigned smem_u32(const void* p){
    return (unsigned)__cvta_generic_to_shared(p);
}
__device__ __forceinline__ void cp16(unsigned s, const void* g){
    asm volatile("cp.async.cg.shared.global [%0], [%1], 16;\n" :: "r"(s), "l"(g));
}
#define CP_COMMIT() asm volatile("cp.async.commit_group;\n")
#define CP_WAIT(n)  asm volatile("cp.async.wait_group %0;\n" :: "n"(n))

__device__ __forceinline__ void mma_tf32(float c[4],
        unsigned a0, unsigned a1, unsigned a2, unsigned a3,
        unsigned b0, unsigned b1){
    asm volatile("mma.sync.aligned.m16n8k8.row.col.f32.tf32.tf32.f32 "
        "{%0,%1,%2,%3},{%4,%5,%6,%7},{%8,%9},{%0,%1,%2,%3};\n"
        : "+f"(c[0]), "+f"(c[1]), "+f"(c[2]), "+f"(c[3])
        : "r"(a0), "r"(a1), "r"(a2), "r"(a3), "r"(b0), "r"(b1));
}

__device__ __forceinline__ float warpReduceSum(float v){
    #pragma unroll
    for (int o=16;o;o>>=1) v += __shfl_xor_sync(0xffffffffu, v, o);
    return v;
}
__device__ __forceinline__ float warpReduceMax(float v){
    #pragma unroll
    for (int o=16;o;o>>=1) v = fmaxf(v, __shfl_xor_sync(0xffffffffu, v, o));
    return v;
}
__device__ float blockReduceSum(float v){   // 256 threads
    __shared__ float s[8]; __shared__ float tot;
    int lane = threadIdx.x & 31, w = threadIdx.x >> 5;
    v = warpReduceSum(v);
    if (!lane) s[w] = v;
    __syncthreads();
    if (w == 0){
        float t = (lane < 8) ? s[lane] : 0.f;
        t = warpReduceSum(t);
        if (!lane) tot = t;
    }
    __syncthreads();
    return tot;
}
__device__ float blockReduceMax(float v){   // 256 threads
    __shared__ float s[8]; __shared__ float tot;
    int lane = threadIdx.x & 31, w = threadIdx.x >> 5;
    v = warpReduceMax(v);
    if (!lane) s[w] = v;
    __syncthreads();
    if (w == 0){
        float t = (lane < 8) ? s[lane] : -3.0e38f;
        t = warpReduceMax(t);
        if (!lane) tot = t;
    }
    __syncthreads();
    return tot;
}

// ---------------- tf32 GEMM: C[M,N] = alpha * A[M,K] @ op(B) (+ Res) ----------------
// BT=0: B is [K,N] row-major.  BT=1: B is [N,K] row-major (C = A @ B^T).
// CM=0: dense. CM=1: causal skip of fully-masked score tiles. CM=2: causal K-limit (PV).
// Tiles: BM=256, BN=128, BK=32; 8 warps of 64x64; cp.async double buffer.
template<int BT, int CM>
__global__ void __launch_bounds__(256, 1)
gemm_tf32(const float* __restrict__ A, long long sA1, long long sA2, int lda,
          const float* __restrict__ B, long long sB1, long long sB2, int ldb,
          float* __restrict__ C, long long sC1, long long sC2, int ldc,
          const float* __restrict__ Res,
          int K, int npm, int npn, float alpha, int roundOut, int zdiv)
{
    constexpr int BM = 256, BN = 128, BK = 32;
    constexpr int ASTR = 40;                    // A smem row stride (pad 8, 16B aligned)
    constexpr int ASZ  = BM * ASTR;             // 10240 floats
    constexpr int BSTR = BT ? 40 : 136;
    constexpr int BSZ  = BT ? (BN * 40) : (BK * 136);
    extern __shared__ float sm[];

    // grouped rasterization for L2 reuse
    int pid = blockIdx.x;
    const int GROUP = 8;
    int npg = GROUP * npn;
    int gid = pid / npg;
    int firstm = gid * GROUP;
    int gsz = min(GROUP, npm - firstm);
    int pm = firstm + (pid % npg) % gsz;
    int pn = (pid % npg) / gsz;
    int m0 = pm * BM, n0 = pn * BN;
    if (CM == 1 && n0 > m0 + BM - 1) return;    // fully masked score tile

    int z = blockIdx.z;
    const float* Ag = A + (long long)(z / zdiv) * sA1 + (long long)(z % zdiv) * sA2;
    const float* Bg = B + (long long)(z / zdiv) * sB1 + (long long)(z % zdiv) * sB2;
    long long offC = (long long)(z / zdiv) * sC1 + (long long)(z % zdiv) * sC2;
    float* Cg = C + offC;
    const float* Rg = Res ? (Res + offC) : nullptr;

    int KT = K / BK;
    if (CM == 2) KT = min(KT, m0 / BK + BM / BK);

    int tid = threadIdx.x;
    int wid = tid >> 5, lane = tid & 31;
    int wm = (wid & 3) * 64;     // 4 warps along M
    int wn = (wid >> 2) * 64;    // 2 warps along N

    auto loadA = [&](int buf, int kt){
        float* s = sm + buf * ASZ;
        int c = tid & 7;
        int r0 = tid >> 3;
        const float* gp = Ag + (long long)m0 * lda + kt * BK + c * 4;
        #pragma unroll
        for (int w = 0; w < 8; w++){
            int row = r0 + 32 * w;
            cp16(smem_u32(s + row * ASTR + c * 4), gp + (long long)row * lda);
        }
    };
    auto loadB = [&](int buf, int kt){
        float* s = sm + 2 * ASZ + buf * BSZ;
        if (BT){
            int c = tid & 7;
            int r0 = tid >> 3;
            const float* gp = Bg + (long long)n0 * ldb + kt * BK + c * 4;
            #pragma unroll
            for (int w = 0; w < 4; w++){
                int row = r0 + 32 * w;
                cp16(smem_u32(s + row * 40 + c * 4), gp + (long long)row * ldb);
            }
        } else {
            int c = tid & 31;
            int r0 = tid >> 5;
            const float* gp = Bg + (long long)(kt * BK) * ldb + n0 + c * 4;
            #pragma unroll
            for (int w = 0; w < 4; w++){
                int row = r0 + 8 * w;
                cp16(smem_u32(s + row * 136 + c * 4), gp + (long long)row * ldb);
            }
        }
    };

    float acc[4][8][4];
    #pragma unroll
    for (int i=0;i<4;i++)
        #pragma unroll
        for (int j=0;j<8;j++)
            #pragma unroll
            for (int r=0;r<4;r++) acc[i][j][r] = 0.f;

    loadA(0, 0); loadB(0, 0); CP_COMMIT();

    for (int kt = 0; kt < KT; kt++){
        int buf = kt & 1;
        if (kt + 1 < KT){
            loadA(buf ^ 1, kt + 1); loadB(buf ^ 1, kt + 1);
            CP_COMMIT();
            CP_WAIT(1);
        } else {
            CP_WAIT(0);
        }
        __syncthreads();
        const float* sa = sm + buf * ASZ;
        const float* sb = sm + 2 * ASZ + buf * BSZ;

        #pragma unroll
        for (int ks = 0; ks < 4; ks++){
            int kk = ks * 8;
            unsigned a[4][4];
            #pragma unroll
            for (int mi = 0; mi < 4; mi++){
                const float* ap = sa + (wm + mi * 16 + (lane >> 2)) * ASTR + kk + (lane & 3);
                a[mi][0] = __float_as_uint(ap[0]);
                a[mi][1] = __float_as_uint(ap[8 * ASTR]);
                a[mi][2] = __float_as_uint(ap[4]);
                a[mi][3] = __float_as_uint(ap[8 * ASTR + 4]);
            }
            #pragma unroll
            for (int ni = 0; ni < 8; ni++){
                unsigned b0, b1;
                if (BT){
                    const float* bp = sb + (wn + ni * 8 + (lane >> 2)) * 40 + kk + (lane & 3);
                    b0 = __float_as_uint(bp[0]);
                    b1 = __float_as_uint(bp[4]);
                } else {
                    const float* bp = sb + (kk + (lane & 3)) * 136 + wn + ni * 8 + (lane >> 2);
                    b0 = __float_as_uint(bp[0]);
                    b1 = __float_as_uint(bp[4 * 136]);
                }
                #pragma unroll
                for (int mi = 0; mi < 4; mi++)
                    mma_tf32(acc[mi][ni], a[mi][0], a[mi][1], a[mi][2], a[mi][3], b0, b1);
            }
        }
        __syncthreads();
    }

    // epilogue
    #pragma unroll
    for (int mi = 0; mi < 4; mi++){
        #pragma unroll
        for (int ni = 0; ni < 8; ni++){
            int row = m0 + wm + mi * 16 + (lane >> 2);
            int col = n0 + wn + ni * 8 + (lane & 3) * 2;
            float v0 = acc[mi][ni][0] * alpha;
            float v1 = acc[mi][ni][1] * alpha;
            float v2 = acc[mi][ni][2] * alpha;
            float v3 = acc[mi][ni][3] * alpha;
            if (Rg){
                float2 r01 = *(const float2*)(Rg + (long long)row * ldc + col);
                float2 r23 = *(const float2*)(Rg + (long long)(row + 8) * ldc + col);
                v0 += r01.x; v1 += r01.y; v2 += r23.x; v3 += r23.y;
            }
            if (roundOut){
                v0 = rna_tf32(v0); v1 = rna_tf32(v1);
                v2 = rna_tf32(v2); v3 = rna_tf32(v3);
            }
            *(float2*)(Cg + (long long)row * ldc + col)       = make_float2(v0, v1);
            *(float2*)(Cg + (long long)(row + 8) * ldc + col) = make_float2(v2, v3);
        }
    }
}

// ---------------- small kernels ----------------
__global__ void round4_kernel(const float4* __restrict__ in, float4* __restrict__ out, int n4){
    int i = blockIdx.x * blockDim.x + threadIdx.x;
    int st = gridDim.x * blockDim.x;
    for (; i < n4; i += st){
        float4 v = in[i];
        v.x = rna_tf32(v.x); v.y = rna_tf32(v.y);
        v.z = rna_tf32(v.z); v.w = rna_tf32(v.w);
        out[i] = v;
    }
}

__global__ void rmsnorm_kernel(const float* __restrict__ X, const float* __restrict__ sc,
                               float* __restrict__ O){
    long long base = (long long)blockIdx.x * HIDDEN;
    int tid = threadIdx.x;
    float v[8]; float ss = 0.f;
    #pragma unroll
    for (int i = 0; i < 8; i++){
        v[i] = X[base + tid + i * 256];
        ss += v[i] * v[i];
    }
    ss = blockReduceSum(ss);
    float r = rsqrtf(ss * (1.0f / (float)HIDDEN) + 1e-5f);
    #pragma unroll
    for (int i = 0; i < 8; i++){
        int c = tid + i * 256;
        O[base + c] = rna_tf32(v[i] * r * sc[c]);
    }
}

__global__ void rope_kernel(float* __restrict__ X, const int* __restrict__ pos){
    int id = blockIdx.x * 256 + threadIdx.x;        // NTOK*NHEADS*64 pairs
    if (id >= NTOK * NHEADS * 64) return;
    int i = id & 63;
    int t = id >> 10;
    long long off = ((long long)t << 11) + (long long)((id & 1023) << 1);
    float invf = (float)exp(-(double)i * (log(500000.0) / 64.0));
    float ang = (float)pos[t] * invf;
    float s, c;
    sincosf(ang, &s, &c);
    float2 v = *(float2*)(X + off);
    float r0 = v.x * c - v.y * s;
    float r1 = v.y * c + v.x * s;
    *(float2*)(X + off) = make_float2(rna_tf32(r0), rna_tf32(r1));
}

__global__ void softmax_causal(float* __restrict__ S){
    __shared__ float buf[SEQ];
    int q = blockIdx.x, z = blockIdx.y;
    float* row = S + ((long long)z * SEQ + (long long)q) * SEQ;
    int n = q + 1, tid = threadIdx.x;
    float mx = -3.0e38f;
    for (int j = tid; j < n; j += 256){
        float v = row[j]; buf[j] = v; mx = fmaxf(mx, v);
    }
    mx = blockReduceMax(mx);
    float sum = 0.f;
    for (int j = tid; j < n; j += 256){
        float e = expf(buf[j] - mx); buf[j] = e; sum += e;
    }
    sum = blockReduceSum(sum);
    float inv = 1.0f / sum;
    for (int j = tid; j < n; j += 256) row[j] = rna_tf32(buf[j] * inv);
    for (int j = n + tid; j < SEQ; j += 256) row[j] = 0.f;
}

__global__ void silu_mul(float4* __restrict__ a, const float4* __restrict__ b, int n4){
    int i = blockIdx.x * blockDim.x + threadIdx.x;
    int st = gridDim.x * blockDim.x;
    for (; i < n4; i += st){
        float4 x = a[i], y = b[i];
        float s0 = x.x / (1.0f + expf(-x.x));
        float s1 = x.y / (1.0f + expf(-x.y));
        float s2 = x.z / (1.0f + expf(-x.z));
        float s3 = x.w / (1.0f + expf(-x.w));
        x.x = rna_tf32(s0 * y.x); x.y = rna_tf32(s1 * y.y);
        x.z = rna_tf32(s2 * y.z); x.w = rna_tf32(s3 * y.w);
        a[i] = x;
    }
}

// ---------------- launch ----------------
#define SMEM_N 116736   // (2*10240 + 2*4352)*4
#define SMEM_T 122880   // (2*10240 + 2*5120)*4

extern "C" void kernel_launch(void* const* d_in, const int* in_sizes, int n_in,
                              void* d_out, int out_size)
{
    const float* x   = (const float*)d_in[0];
    const int*   pos = (const int*)d_in[1];
    // d_in[2] = mask (causal tril; computed analytically instead)
    const float* wq  = (const float*)d_in[3];
    const float* wk  = (const float*)d_in[4];
    const float* wv  = (const float*)d_in[5];
    const float* wo  = (const float*)d_in[6];
    const float* asc = (const float*)d_in[7];
    const float* fsc = (const float*)d_in[8];
    const float* w1  = (const float*)d_in[9];
    const float* w3  = (const float*)d_in[10];
    const float* w2  = (const float*)d_in[11];
    float* out = (float*)d_out;

    float *p_xn,*p_q,*p_k,*p_v,*p_ao,*p_h,*p_ffn,*p_sc,*p_g1,*p_g3;
    float *p_wq,*p_wk,*p_wv,*p_wo,*p_w1,*p_w3,*p_w2;
    cudaGetSymbolAddress((void**)&p_xn, g_xnorm);
    cudaGetSymbolAddress((void**)&p_q,  g_q);
    cudaGetSymbolAddress((void**)&p_k,  g_k);
    cudaGetSymbolAddress((void**)&p_v,  g_v);
    cudaGetSymbolAddress((void**)&p_ao, g_attnout);
    cudaGetSymbolAddress((void**)&p_h,  g_h);
    cudaGetSymbolAddress((void**)&p_ffn,g_ffn);
    cudaGetSymbolAddress((void**)&p_sc, g_scores);
    cudaGetSymbolAddress((void**)&p_g1, g_g1);
    cudaGetSymbolAddress((void**)&p_g3, g_g3);
    cudaGetSymbolAddress((void**)&p_wq, g_wq);
    cudaGetSymbolAddress((void**)&p_wk, g_wk);
    cudaGetSymbolAddress((void**)&p_wv, g_wv);
    cudaGetSymbolAddress((void**)&p_wo, g_wo);
    cudaGetSymbolAddress((void**)&p_w1, g_w1);
    cudaGetSymbolAddress((void**)&p_w3, g_w3);
    cudaGetSymbolAddress((void**)&p_w2, g_w2);

    cudaFuncSetAttribute(gemm_tf32<0,0>, cudaFuncAttributeMaxDynamicSharedMemorySize, SMEM_N);
    cudaFuncSetAttribute(gemm_tf32<0,2>, cudaFuncAttributeMaxDynamicSharedMemorySize, SMEM_N);
    cudaFuncSetAttribute(gemm_tf32<1,1>, cudaFuncAttributeMaxDynamicSharedMemorySize, SMEM_T);

    // 1. round weights to tf32 (rna)
    round4_kernel<<<2048,256>>>((const float4*)wq, (float4*)p_wq, HIDDEN*HIDDEN/4);
    round4_kernel<<<2048,256>>>((const float4*)wk, (float4*)p_wk, HIDDEN*HIDDEN/4);
    round4_kernel<<<2048,256>>>((const float4*)wv, (float4*)p_wv, HIDDEN*HIDDEN/4);
    round4_kernel<<<2048,256>>>((const float4*)wo, (float4*)p_wo, HIDDEN*HIDDEN/4);
    round4_kernel<<<4096,256>>>((const float4*)w1, (float4*)p_w1, HIDDEN*FFDIM/4);
    round4_kernel<<<4096,256>>>((const float4*)w3, (float4*)p_w3, HIDDEN*FFDIM/4);
    round4_kernel<<<4096,256>>>((const float4*)w2, (float4*)p_w2, FFDIM*HIDDEN/4);

    // 2. rmsnorm (attn)
    rmsnorm_kernel<<<NTOK,256>>>(x, asc, p_xn);

    // 3. Q/K/V projections  (M=4096, N=2048, K=2048)
    dim3 gProj(16*16, 1, 1);
    gemm_tf32<0,0><<<gProj,256,SMEM_N>>>(p_xn,0,0,HIDDEN, p_wq,0,0,HIDDEN, p_q,0,0,HIDDEN,
                                         nullptr, HIDDEN, 16,16, 1.f, 0, 1);
    gemm_tf32<0,0><<<gProj,256,SMEM_N>>>(p_xn,0,0,HIDDEN, p_wk,0,0,HIDDEN, p_k,0,0,HIDDEN,
                                         nullptr, HIDDEN, 16,16, 1.f, 0, 1);
    gemm_tf32<0,0><<<gProj,256,SMEM_N>>>(p_xn,0,0,HIDDEN, p_wv,0,0,HIDDEN, p_v,0,0,HIDDEN,
                                         nullptr, HIDDEN, 16,16, 1.f, 1, 1);

    // 4. RoPE on q, k
    rope_kernel<<<16384,256>>>(p_q, pos);
    rope_kernel<<<16384,256>>>(p_k, pos);

    // 5. scores = alpha * Q @ K^T  (batched over 32 b*h, causal tile skip)
    dim3 gQK(8*16, 1, BATCHN*NHEADS);
    gemm_tf32<1,1><<<gQK,256,SMEM_T>>>(
        p_q, (long long)SEQ*HIDDEN, 128LL, HIDDEN,
        p_k, (long long)SEQ*HIDDEN, 128LL, HIDDEN,
        p_sc, (long long)NHEADS*SEQ*SEQ, (long long)SEQ*SEQ, SEQ,
        nullptr, HDIM, 8, 16, 0.08838834764831845f, 0, NHEADS);

    // 6. causal softmax (in place, rounds P to tf32, zeros tail)
    softmax_causal<<<dim3(SEQ, BATCHN*NHEADS),256>>>(p_sc);

    // 7. attn_out = P @ V  (batched, causal K-limit)
    dim3 gPV(8, 1, BATCHN*NHEADS);
    gemm_tf32<0,2><<<gPV,256,SMEM_N>>>(
        p_sc, (long long)NHEADS*SEQ*SEQ, (long long)SEQ*SEQ, SEQ,
        p_v,  (long long)SEQ*HIDDEN, 128LL, HIDDEN,
        p_ao, (long long)SEQ*HIDDEN, 128LL, HIDDEN,
        nullptr, SEQ, 8, 1, 1.f, 1, NHEADS);

    // 8. h = x + attn_out @ wo
    gemm_tf32<0,0><<<gProj,256,SMEM_N>>>(p_ao,0,0,HIDDEN, p_wo,0,0,HIDDEN, p_h,0,0,HIDDEN,
                                         x, HIDDEN, 16,16, 1.f, 0, 1);

    // 9. rmsnorm (ffn)
    rmsnorm_kernel<<<NTOK,256>>>(p_h, fsc, p_ffn);

    // 10. g1 = ff @ w1 ; g3 = ff @ w3   (M=4096, N=5632, K=2048)
    dim3 gFF(16*44, 1, 1);
    gemm_tf32<0,0><<<gFF,256,SMEM_N>>>(p_ffn,0,0,HIDDEN, p_w1,0,0,FFDIM, p_g1,0,0,FFDIM,
                                       nullptr, HIDDEN, 16,44, 1.f, 0, 1);
    gemm_tf32<0,0><<<gFF,256,SMEM_N>>>(p_ffn,0,0,HIDDEN, p_w3,0,0,FFDIM, p_g3,0,0,FFDIM,
                                       nullptr, HIDDEN, 16,44, 1.f, 0, 1);

    // 11. g1 = silu(g1) * g3
    silu_mul<<<4096,256>>>((float4*)p_g1, (const float4*)p_g3, (int)((size_t)NTOK*FFDIM/4));

    // 12. out = h + g1 @ w2   (M=4096, N=2048, K=5632)
    gemm_tf32<0,0><<<gProj,256,SMEM_N>>>(p_g1,0,0,FFDIM, p_w2,0,0,HIDDEN, out,0,0,HIDDEN,
                                         p_h, FFDIM, 16,16, 1.f, 0, 1);
}

// round 4
// speedup vs baseline: 1.2896x; 1.2896x over previous
#include <cuda_runtime.h>
#include <cstdint>
#include <math.h>

#define HIDDEN 2048
#define NHEADS 16
#define HDIM 128
#define FFDIM 5632
#define BATCHN 2
#define SEQ 2048
#define NTOK (BATCHN*SEQ)   // 4096

// ---------------- scratch (device globals: no allocation allowed) ----------------
__device__ float g_xnorm[NTOK*HIDDEN];
__device__ float g_q[NTOK*HIDDEN];
__device__ float g_k[NTOK*HIDDEN];
__device__ float g_v[NTOK*HIDDEN];
__device__ float g_attnout[NTOK*HIDDEN];
__device__ float g_h[NTOK*HIDDEN];
__device__ float g_ffn[NTOK*HIDDEN];
__device__ float g_g1[(size_t)NTOK*FFDIM];
__device__ float g_g3[(size_t)NTOK*FFDIM];
__device__ float g_invf[64];
// tf32-rounded weights
__device__ float g_wq[HIDDEN*HIDDEN];
__device__ float g_wk[HIDDEN*HIDDEN];
__device__ float g_wv[HIDDEN*HIDDEN];
__device__ float g_wo[HIDDEN*HIDDEN];
__device__ float g_w1[(size_t)HIDDEN*FFDIM];
__device__ float g_w3[(size_t)HIDDEN*FFDIM];
__device__ float g_w2[(size_t)FFDIM*HIDDEN];

// ---------------- helpers ----------------
__device__ __forceinline__ float rna_tf32(float x){
    unsigned r; asm("cvt.rna.tf32.f32 %0, %1;" : "=r"(r) : "f"(x));
    return __uint_as_float(r);
}
__device__ __forceinline__ unsigned smem_u32(const void* p){
    return (unsigned)__cvta_generic_to_shared(p);
}
__device__ __forceinline__ void cp16(unsigned s, const void* g){
    asm volatile("cp.async.cg.shared.global [%0], [%1], 16;\n" :: "r"(s), "l"(g));
}
#define CP_COMMIT() asm volatile("cp.async.commit_group;\n")
#define CP_WAIT(n)  asm volatile("cp.async.wait_group %0;\n" :: "n"(n))

__device__ __forceinline__ void mma_tf32(float c[4],
        unsigned a0, unsigned a1, unsigned a2, unsigned a3,
        unsigned b0, unsigned b1){
    asm volatile("mma.sync.aligned.m16n8k8.row.col.f32.tf32.tf32.f32 "
        "{%0,%1,%2,%3},{%4,%5,%6,%7},{%8,%9},{%0,%1,%2,%3};\n"
        : "+f"(c[0]), "+f"(c[1]), "+f"(c[2]), "+f"(c[3])
        : "r"(a0), "r"(a1), "r"(a2), "r"(a3), "r"(b0), "r"(b1));
}

__device__ __forceinline__ float warpReduceSum(float v){
    #pragma unroll
    for (int o=16;o;o>>=1) v += __shfl_xor_sync(0xffffffffu, v, o);
    return v;
}
__device__ float blockReduceSum(float v){   // 256 threads
    __shared__ float s[8]; __shared__ float tot;
    int lane = threadIdx.x & 31, w = threadIdx.x >> 5;
    v = warpReduceSum(v);
    if (!lane) s[w] = v;
    __syncthreads();
    if (w == 0){
        float t = (lane < 8) ? s[lane] : 0.f;
        t = warpReduceSum(t);
        if (!lane) tot = t;
    }
    __syncthreads();
    return tot;
}

// ---------------- tf32 GEMM: C[M,N] = A[M,K] @ B[K,N] (+ Res) ----------------
// Tiles: BM=256, BN=128, BK=32; 8 warps of 64x64; cp.async double buffer.
// doRope: apply RoPE to output pairs (used for Q/K projections) then tf32-round.
__global__ void __launch_bounds__(256, 1)
gemm_tf32(const float* __restrict__ A, int lda,
          const float* __restrict__ B, int ldb,
          float* __restrict__ C, int ldc,
          const float* __restrict__ Res,
          int K, int npm, int npn, int roundOut,
          const int* __restrict__ pos, int doRope)
{
    constexpr int BM = 256, BN = 128, BK = 32;
    constexpr int ASTR = 40;
    constexpr int ASZ  = BM * ASTR;             // 10240 floats
    constexpr int BSZ  = BK * 136;
    extern __shared__ float sm[];

    // grouped rasterization for L2 reuse
    int pid = blockIdx.x;
    const int GROUP = 8;
    int npg = GROUP * npn;
    int gid = pid / npg;
    int firstm = gid * GROUP;
    int gsz = min(GROUP, npm - firstm);
    int pm = firstm + (pid % npg) % gsz;
    int pn = (pid % npg) / gsz;
    int m0 = pm * BM, n0 = pn * BN;

    int KT = K / BK;
    int tid = threadIdx.x;
    int wid = tid >> 5, lane = tid & 31;
    int wm = (wid & 3) * 64;
    int wn = (wid >> 2) * 64;

    auto loadA = [&](int buf, int kt){
        float* s = sm + buf * ASZ;
        int c = tid & 7;
        int r0 = tid >> 3;
        const float* gp = A + (long long)m0 * lda + kt * BK + c * 4;
        #pragma unroll
        for (int w = 0; w < 8; w++){
            int row = r0 + 32 * w;
            cp16(smem_u32(s + row * ASTR + c * 4), gp + (long long)row * lda);
        }
    };
    auto loadB = [&](int buf, int kt){
        float* s = sm + 2 * ASZ + buf * BSZ;
        int c = tid & 31;
        int r0 = tid >> 5;
        const float* gp = B + (long long)(kt * BK) * ldb + n0 + c * 4;
        #pragma unroll
        for (int w = 0; w < 4; w++){
            int row = r0 + 8 * w;
            cp16(smem_u32(s + row * 136 + c * 4), gp + (long long)row * ldb);
        }
    };

    float acc[4][8][4];
    #pragma unroll
    for (int i=0;i<4;i++)
        #pragma unroll
        for (int j=0;j<8;j++)
            #pragma unroll
            for (int r=0;r<4;r++) acc[i][j][r] = 0.f;

    loadA(0, 0); loadB(0, 0); CP_COMMIT();

    for (int kt = 0; kt < KT; kt++){
        int buf = kt & 1;
        if (kt + 1 < KT){
            loadA(buf ^ 1, kt + 1); loadB(buf ^ 1, kt + 1);
            CP_COMMIT();
            CP_WAIT(1);
        } else {
            CP_WAIT(0);
        }
        __syncthreads();
        const float* sa = sm + buf * ASZ;
        const float* sb = sm + 2 * ASZ + buf * BSZ;

        #pragma unroll
        for (int ks = 0; ks < 4; ks++){
            int kk = ks * 8;
            unsigned a[4][4];
            #pragma unroll
            for (int mi = 0; mi < 4; mi++){
                const float* ap = sa + (wm + mi * 16 + (lane >> 2)) * ASTR + kk + (lane & 3);
                a[mi][0] = __float_as_uint(ap[0]);
                a[mi][1] = __float_as_uint(ap[8 * ASTR]);
                a[mi][2] = __float_as_uint(ap[4]);
                a[mi][3] = __float_as_uint(ap[8 * ASTR + 4]);
            }
            #pragma unroll
            for (int ni = 0; ni < 8; ni++){
                const float* bp = sb + (kk + (lane & 3)) * 136 + wn + ni * 8 + (lane >> 2);
                unsigned b0 = __float_as_uint(bp[0]);
                unsigned b1 = __float_as_uint(bp[4 * 136]);
                #pragma unroll
                for (int mi = 0; mi < 4; mi++)
                    mma_tf32(acc[mi][ni], a[mi][0], a[mi][1], a[mi][2], a[mi][3], b0, b1);
            }
        }
        __syncthreads();
    }

    // epilogue
    #pragma unroll
    for (int mi = 0; mi < 4; mi++){
        #pragma unroll
        for (int ni = 0; ni < 8; ni++){
            int row = m0 + wm + mi * 16 + (lane >> 2);
            int col = n0 + wn + ni * 8 + (lane & 3) * 2;
            float v0 = acc[mi][ni][0];
            float v1 = acc[mi][ni][1];
            float v2 = acc[mi][ni][2];
            float v3 = acc[mi][ni][3];
            if (Res){
                float2 r01 = *(const float2*)(Res + (long long)row * ldc + col);
                float2 r23 = *(const float2*)(Res + (long long)(row + 8) * ldc + col);
                v0 += r01.x; v1 += r01.y; v2 += r23.x; v3 += r23.y;
            }
            if (doRope){
                int i = (col & 127) >> 1;
                float invf = g_invf[i];
                float a0 = (float)pos[row] * invf;
                float a1 = (float)pos[row + 8] * invf;
                float s0, c0, s1, c1;
                sincosf(a0, &s0, &c0);
                sincosf(a1, &s1, &c1);
                float t0 = v0 * c0 - v1 * s0;
                float t1 = v1 * c0 + v0 * s0;
                float t2 = v2 * c1 - v3 * s1;
                float t3 = v3 * c1 + v2 * s1;
                v0 = t0; v1 = t1; v2 = t2; v3 = t3;
            }
            if (roundOut | doRope){
                v0 = rna_tf32(v0); v1 = rna_tf32(v1);
                v2 = rna_tf32(v2); v3 = rna_tf32(v3);
            }
            *(float2*)(C + (long long)row * ldc + col)       = make_float2(v0, v1);
            *(float2*)(C + (long long)(row + 8) * ldc + col) = make_float2(v2, v3);
        }
    }
}

// ---------------- flash attention (v2: gemm-style double buffer, 64-key tiles) ----
// Per CTA: one (b,h) and one 128-row q tile. 8 warps, each owns 16 q rows.
#define KSTR 140
#define VSTR 136
#define PSTR 76
#define KTILE 64
#define FLASH_SMEM ((2*KTILE*KSTR + 2*KTILE*VSTR + 8*16*PSTR)*4)   // 180224 B

__global__ void __launch_bounds__(256, 1)
flash_attn(const float* __restrict__ Q, const float* __restrict__ K,
           const float* __restrict__ V, float* __restrict__ O,
           float alpha)
{
    extern __shared__ float sm[];
    float* sKb = sm;                        // 2 * 64*140
    float* sVb = sm + 2*KTILE*KSTR;         // 2 * 64*136
    float* sP  = sVb + 2*KTILE*VSTR;        // 8*16*76

    int z = blockIdx.y;               // b*16+h
    int b = z >> 4, h = z & 15;
    int qt = (gridDim.x - 1) - blockIdx.x;   // heavy tiles first
    int q0 = qt * 128;
    const float* Qg = Q + ((long long)b * SEQ) * HIDDEN + h * HDIM;
    const float* Kg = K + ((long long)b * SEQ) * HIDDEN + h * HDIM;
    const float* Vg = V + ((long long)b * SEQ) * HIDDEN + h * HDIM;
    float* Og = O + ((long long)b * SEQ) * HIDDEN + h * HDIM;

    int tid = threadIdx.x, wid = tid >> 5, lane = tid & 31;
    int rl = lane >> 2, l3 = lane & 3;
    int qr = q0 + wid * 16;
    float* sPw = sP + wid * 16 * PSTR;

    // Q fragments in registers (already tf32-rounded + rope'd by producer)
    unsigned qf[16][4];
    #pragma unroll
    for (int ks = 0; ks < 16; ks++){
        const float* p0 = Qg + (long long)(qr + rl) * HIDDEN + ks * 8 + l3;
        const float* p1 = Qg + (long long)(qr + rl + 8) * HIDDEN + ks * 8 + l3;
        qf[ks][0] = __float_as_uint(p0[0]);
        qf[ks][1] = __float_as_uint(p1[0]);
        qf[ks][2] = __float_as_uint(p0[4]);
        qf[ks][3] = __float_as_uint(p1[4]);
    }

    float Oa[16][4];
    #pragma unroll
    for (int ni = 0; ni < 16; ni++){
        Oa[ni][0] = 0.f; Oa[ni][1] = 0.f; Oa[ni][2] = 0.f; Oa[ni][3] = 0.f;
    }
    float m0r = -1e30f, m1r = -1e30f, l0r = 0.f, l1r = 0.f;

    // one commit group per tile: K then V (64 rows x 128 floats each)
    auto loadKV = [&](int buf, int t){
        int c = tid & 31, r0 = tid >> 5;
        const float* kp = Kg + (long long)(t * KTILE) * HIDDEN + c * 4;
        const float* vp = Vg + (long long)(t * KTILE) * HIDDEN + c * 4;
        float* dk = sKb + buf * KTILE * KSTR;
        float* dv = sVb + buf * KTILE * VSTR;
        #pragma unroll
        for (int w = 0; w < 8; w++){
            int row = r0 + 8 * w;
            cp16(smem_u32(dk + row * KSTR + c * 4), kp + (long long)row * HIDDEN);
        }
        #pragma unroll
        for (int w = 0; w < 8; w++){
            int row = r0 + 8 * w;
            cp16(smem_u32(dv + row * VSTR + c * 4), vp + (long long)row * HIDDEN);
        }
    };

    int nt = 2 * qt + 2;
    loadKV(0, 0); CP_COMMIT();

    for (int t = 0; t < nt; t++){
        int buf = t & 1;
        if (t + 1 < nt){
            loadKV(buf ^ 1, t + 1);
            CP_COMMIT();
            CP_WAIT(1);
        } else {
            CP_WAIT(0);
        }
        __syncthreads();
        const float* cK = sKb + buf * KTILE * KSTR;
        const float* cV = sVb + buf * KTILE * VSTR;
        int diag = (t >= 2 * qt);
        int k0 = t * KTILE;

        // S = Q @ K^T over 64 keys
        float Sa[8][4];
        #pragma unroll
        for (int ni = 0; ni < 8; ni++){
            Sa[ni][0]=0.f; Sa[ni][1]=0.f; Sa[ni][2]=0.f; Sa[ni][3]=0.f;
        }
        #pragma unroll
        for (int ks = 0; ks < 16; ks++){
            #pragma unroll
            for (int ni = 0; ni < 8; ni++){
                int n = ni * 8 + rl;
                unsigned b0 = __float_as_uint(cK[n * KSTR + ks * 8 + l3]);
                unsigned b1 = __float_as_uint(cK[n * KSTR + ks * 8 + 4 + l3]);
                mma_tf32(Sa[ni], qf[ks][0], qf[ks][1], qf[ks][2], qf[ks][3], b0, b1);
            }
        }

        // scale + causal mask + row max
        int r0g = qr + rl, r1g = qr + rl + 8;
        float mx0 = -1e30f, mx1 = -1e30f;
        #pragma unroll
        for (int ni = 0; ni < 8; ni++){
            float x0 = Sa[ni][0] * alpha, x1 = Sa[ni][1] * alpha;
            float x2 = Sa[ni][2] * alpha, x3 = Sa[ni][3] * alpha;
            if (diag){
                int kg = k0 + ni * 8 + 2 * l3;
                if (kg     > r0g) x0 = -1e30f;
                if (kg + 1 > r0g) x1 = -1e30f;
                if (kg     > r1g) x2 = -1e30f;
                if (kg + 1 > r1g) x3 = -1e30f;
            }
            Sa[ni][0]=x0; Sa[ni][1]=x1; Sa[ni][2]=x2; Sa[ni][3]=x3;
            mx0 = fmaxf(mx0, fmaxf(x0, x1));
            mx1 = fmaxf(mx1, fmaxf(x2, x3));
        }
        mx0 = fmaxf(mx0, __shfl_xor_sync(0xffffffffu, mx0, 1));
        mx0 = fmaxf(mx0, __shfl_xor_sync(0xffffffffu, mx0, 2));
        mx1 = fmaxf(mx1, __shfl_xor_sync(0xffffffffu, mx1, 1));
        mx1 = fmaxf(mx1, __shfl_xor_sync(0xffffffffu, mx1, 2));

        float mn0 = fmaxf(m0r, mx0), mn1 = fmaxf(m1r, mx1);
        float cr0 = __expf(m0r - mn0), cr1 = __expf(m1r - mn1);
        m0r = mn0; m1r = mn1;
        l0r *= cr0; l1r *= cr1;
        #pragma unroll
        for (int ni = 0; ni < 16; ni++){
            Oa[ni][0] *= cr0; Oa[ni][1] *= cr0;
            Oa[ni][2] *= cr1; Oa[ni][3] *= cr1;
        }
        float rs0 = 0.f, rs1 = 0.f;
        #pragma unroll
        for (int ni = 0; ni < 8; ni++){
            float e0 = __expf(Sa[ni][0] - mn0);
            float e1 = __expf(Sa[ni][1] - mn0);
            float e2 = __expf(Sa[ni][2] - mn1);
            float e3 = __expf(Sa[ni][3] - mn1);
            rs0 += e0 + e1; rs1 += e2 + e3;
            int colp = ni * 8 + 2 * l3;
            *(float2*)(sPw + rl * PSTR + colp)       = make_float2(rna_tf32(e0), rna_tf32(e1));
            *(float2*)(sPw + (rl + 8) * PSTR + colp) = make_float2(rna_tf32(e2), rna_tf32(e3));
        }
        rs0 += __shfl_xor_sync(0xffffffffu, rs0, 1);
        rs0 += __shfl_xor_sync(0xffffffffu, rs0, 2);
        rs1 += __shfl_xor_sync(0xffffffffu, rs1, 1);
        rs1 += __shfl_xor_sync(0xffffffffu, rs1, 2);
        l0r += rs0; l1r += rs1;
        __syncwarp();

        // O += P @ V  (64 keys => ks 0..7)
        #pragma unroll
        for (int ks = 0; ks < 8; ks++){
            unsigned a0 = __float_as_uint(sPw[rl * PSTR + ks * 8 + l3]);
            unsigned a1 = __float_as_uint(sPw[(rl + 8) * PSTR + ks * 8 + l3]);
            unsigned a2 = __float_as_uint(sPw[rl * PSTR + ks * 8 + 4 + l3]);
            unsigned a3 = __float_as_uint(sPw[(rl + 8) * PSTR + ks * 8 + 4 + l3]);
            #pragma unroll
            for (int ni = 0; ni < 16; ni++){
                unsigned b0 = __float_as_uint(cV[(ks * 8 + l3) * VSTR + ni * 8 + rl]);
                unsigned b1 = __float_as_uint(cV[(ks * 8 + 4 + l3) * VSTR + ni * 8 + rl]);
                mma_tf32(Oa[ni], a0, a1, a2, a3, b0, b1);
            }
        }
        __syncthreads();   // all warps done with cK/cV before prefetch overwrites
    }

    // normalize + write (rounded: feeds WO gemm)
    float inv0 = 1.0f / l0r, inv1 = 1.0f / l1r;
    #pragma unroll
    for (int ni = 0; ni < 16; ni++){
        int col = ni * 8 + 2 * l3;
        *(float2*)(Og + (long long)(qr + rl) * HIDDEN + col) =
            make_float2(rna_tf32(Oa[ni][0] * inv0), rna_tf32(Oa[ni][1] * inv0));
        *(float2*)(Og + (long long)(qr + rl + 8) * HIDDEN + col) =
            make_float2(rna_tf32(Oa[ni][2] * inv1), rna_tf32(Oa[ni][3] * inv1));
    }
}

// ---------------- small kernels ----------------
__global__ void round_all(const float4* s0, float4* d0, const float4* s1, float4* d1,
                          const float4* s2, float4* d2, const float4* s3, float4* d3,
                          const float4* s4, float4* d4, const float4* s5, float4* d5,
                          const float4* s6, float4* d6)
{
    int gid = blockIdx.x * blockDim.x + threadIdx.x;
    int st = gridDim.x * blockDim.x;
    if (gid < 64) g_invf[gid] = (float)exp(-(double)gid * (log(500000.0) / 64.0));
    const int NA = HIDDEN * HIDDEN / 4;          // 1048576
    const int NB = HIDDEN * FFDIM / 4;           // 2883584
    const float4* srcs[7] = {s0, s1, s2, s3, s4, s5, s6};
    float4*       dsts[7] = {d0, d1, d2, d3, d4, d5, d6};
    #pragma unroll
    for (int seg = 0; seg < 7; seg++){
        int n = (seg < 4) ? NA : NB;
        const float4* s = srcs[seg];
        float4* d = dsts[seg];
        for (int i = gid; i < n; i += st){
            float4 v = s[i];
            v.x = rna_tf32(v.x); v.y = rna_tf32(v.y);
            v.z = rna_tf32(v.z); v.w = rna_tf32(v.w);
            d[i] = v;
        }
    }
}

__global__ void rmsnorm_kernel(const float* __restrict__ X, const float* __restrict__ sc,
                               float* __restrict__ O){
    long long base = (long long)blockIdx.x * HIDDEN;
    int tid = threadIdx.x;
    float v[8]; float ss = 0.f;
    #pragma unroll
    for (int i = 0; i < 8; i++){
        v[i] = X[base + tid + i * 256];
        ss += v[i] * v[i];
    }
    ss = blockReduceSum(ss);
    float r = rsqrtf(ss * (1.0f / (float)HIDDEN) + 1e-5f);
    #pragma unroll
    for (int i = 0; i < 8; i++){
        int c = tid + i * 256;
        O[base + c] = rna_tf32(v[i] * r * sc[c]);
    }
}

__global__ void silu_mul(float4* __restrict__ a, const float4* __restrict__ b, int n4){
    int i = blockIdx.x * blockDim.x + threadIdx.x;
    int st = gridDim.x * blockDim.x;
    for (; i < n4; i += st){
        float4 x = a[i], y = b[i];
        float s0 = x.x / (1.0f + expf(-x.x));
        float s1 = x.y / (1.0f + expf(-x.y));
        float s2 = x.z / (1.0f + expf(-x.z));
        float s3 = x.w / (1.0f + expf(-x.w));
        x.x = rna_tf32(s0 * y.x); x.y = rna_tf32(s1 * y.y);
        x.z = rna_tf32(s2 * y.z); x.w = rna_tf32(s3 * y.w);
        a[i] = x;
    }
}

// ---------------- launch ----------------
#define SMEM_N 116736   // (2*10240 + 2*4352)*4

extern "C" void kernel_launch(void* const* d_in, const int* in_sizes, int n_in,
                              void* d_out, int out_size)
{
    const float* x   = (const float*)d_in[0];
    const int*   pos = (const int*)d_in[1];
    // d_in[2] = mask (causal; handled analytically)
    const float* wq  = (const float*)d_in[3];
    const float* wk  = (const float*)d_in[4];
    const float* wv  = (const float*)d_in[5];
    const float* wo  = (const float*)d_in[6];
    const float* asc = (const float*)d_in[7];
    const float* fsc = (const float*)d_in[8];
    const float* w1  = (const float*)d_in[9];
    const float* w3  = (const float*)d_in[10];
    const float* w2  = (const float*)d_in[11];
    float* out = (float*)d_out;

    float *p_xn,*p_q,*p_k,*p_v,*p_ao,*p_h,*p_ffn,*p_g1,*p_g3;
    float *p_wq,*p_wk,*p_wv,*p_wo,*p_w1,*p_w3,*p_w2;
    cudaGetSymbolAddress((void**)&p_xn, g_xnorm);
    cudaGetSymbolAddress((void**)&p_q,  g_q);
    cudaGetSymbolAddress((void**)&p_k,  g_k);
    cudaGetSymbolAddress((void**)&p_v,  g_v);
    cudaGetSymbolAddress((void**)&p_ao, g_attnout);
    cudaGetSymbolAddress((void**)&p_h,  g_h);
    cudaGetSymbolAddress((void**)&p_ffn,g_ffn);
    cudaGetSymbolAddress((void**)&p_g1, g_g1);
    cudaGetSymbolAddress((void**)&p_g3, g_g3);
    cudaGetSymbolAddress((void**)&p_wq, g_wq);
    cudaGetSymbolAddress((void**)&p_wk, g_wk);
    cudaGetSymbolAddress((void**)&p_wv, g_wv);
    cudaGetSymbolAddress((void**)&p_wo, g_wo);
    cudaGetSymbolAddress((void**)&p_w1, g_w1);
    cudaGetSymbolAddress((void**)&p_w3, g_w3);
    cudaGetSymbolAddress((void**)&p_w2, g_w2);

    cudaFuncSetAttribute(gemm_tf32, cudaFuncAttributeMaxDynamicSharedMemorySize, SMEM_N);
    cudaFuncSetAttribute(flash_attn, cudaFuncAttributeMaxDynamicSharedMemorySize, FLASH_SMEM);

    // 0. round weights to tf32 (rna) + inv_freq table
    round_all<<<4096,256>>>((const float4*)wq, (float4*)p_wq,
                            (const float4*)wk, (float4*)p_wk,
                            (const float4*)wv, (float4*)p_wv,
                            (const float4*)wo, (float4*)p_wo,
                            (const float4*)w1, (float4*)p_w1,
                            (const float4*)w3, (float4*)p_w3,
                            (const float4*)w2, (float4*)p_w2);

    // 1. rmsnorm (attn)
    rmsnorm_kernel<<<NTOK,256>>>(x, asc, p_xn);

    // 2-4. Q/K/V projections (rope fused into Q,K epilogues)
    dim3 gProj(16*16, 1, 1);
    gemm_tf32<<<gProj,256,SMEM_N>>>(p_xn,HIDDEN, p_wq,HIDDEN, p_q,HIDDEN,
                                    nullptr, HIDDEN, 16,16, 0, pos, 1);
    gemm_tf32<<<gProj,256,SMEM_N>>>(p_xn,HIDDEN, p_wk,HIDDEN, p_k,HIDDEN,
                                    nullptr, HIDDEN, 16,16, 0, pos, 1);
    gemm_tf32<<<gProj,256,SMEM_N>>>(p_xn,HIDDEN, p_wv,HIDDEN, p_v,HIDDEN,
                                    nullptr, HIDDEN, 16,16, 1, nullptr, 0);

    // 5. flash attention (profiled by ncu -s 5)
    flash_attn<<<dim3(16, BATCHN*NHEADS),256,FLASH_SMEM>>>(
        p_q, p_k, p_v, p_ao, 0.08838834764831845f);

    // 6. h = x + attn_out @ wo
    gemm_tf32<<<gProj,256,SMEM_N>>>(p_ao,HIDDEN, p_wo,HIDDEN, p_h,HIDDEN,
                                    x, HIDDEN, 16,16, 0, nullptr, 0);

    // 7. rmsnorm (ffn)
    rmsnorm_kernel<<<NTOK,256>>>(p_h, fsc, p_ffn);

    // 8-9. g1 = ff @ w1 ; g3 = ff @ w3
    dim3 gFF(16*44, 1, 1);
    gemm_tf32<<<gFF,256,SMEM_N>>>(p_ffn,HIDDEN, p_w1,FFDIM, p_g1,FFDIM,
                                  nullptr, HIDDEN, 16,44, 0, nullptr, 0);
    gemm_tf32<<<gFF,256,SMEM_N>>>(p_ffn,HIDDEN, p_w3,FFDIM, p_g3,FFDIM,
                                  nullptr, HIDDEN, 16,44, 0, nullptr, 0);

    // 10. g1 = silu(g1) * g3
    silu_mul<<<4096,256>>>((float4*)p_g1, (const float4*)p_g3, (int)((size_t)NTOK*FFDIM/4));

    // 11. out = h + g1 @ w2
    gemm_tf32<<<gProj,256,SMEM_N>>>(p_g1,FFDIM, p_w2,HIDDEN, out,HIDDEN,
                                    p_h, FFDIM, 16,16, 0, nullptr, 0);
}

// round 5
// speedup vs baseline: 1.3688x; 1.0614x over previous
#include <cuda_runtime.h>
#include <cstdint>
#include <math.h>

#define HIDDEN 2048
#define NHEADS 16
#define HDIM 128
#define FFDIM 5632
#define BATCHN 2
#define SEQ 2048
#define NTOK (BATCHN*SEQ)   // 4096

// ---------------- scratch (device globals: no allocation allowed) ----------------
__device__ float g_xnorm[NTOK*HIDDEN];
__device__ float g_q[NTOK*HIDDEN];
__device__ float g_k[NTOK*HIDDEN];
__device__ float g_v[NTOK*HIDDEN];
__device__ float g_attnout[NTOK*HIDDEN];
__device__ float g_h[NTOK*HIDDEN];
__device__ float g_ffn[NTOK*HIDDEN];
__device__ float g_g1[(size_t)NTOK*FFDIM];
__device__ float g_g3[(size_t)NTOK*FFDIM];
__device__ float g_invf[64];
// tf32-rounded weights
__device__ float g_wq[HIDDEN*HIDDEN];
__device__ float g_wk[HIDDEN*HIDDEN];
__device__ float g_wv[HIDDEN*HIDDEN];
__device__ float g_wo[HIDDEN*HIDDEN];
__device__ float g_w1[(size_t)HIDDEN*FFDIM];
__device__ float g_w3[(size_t)HIDDEN*FFDIM];
__device__ float g_w2[(size_t)FFDIM*HIDDEN];

// ---------------- helpers ----------------
__device__ __forceinline__ float rna_tf32(float x){
    unsigned r; asm("cvt.rna.tf32.f32 %0, %1;" : "=r"(r) : "f"(x));
    return __uint_as_float(r);
}
__device__ __forceinline__ unsigned smem_u32(const void* p){
    return (unsigned)__cvta_generic_to_shared(p);
}
__device__ __forceinline__ void cp16(unsigned s, const void* g){
    asm volatile("cp.async.cg.shared.global [%0], [%1], 16;\n" :: "r"(s), "l"(g));
}
#define CP_COMMIT() asm volatile("cp.async.commit_group;\n")
#define CP_WAIT(n)  asm volatile("cp.async.wait_group %0;\n" :: "n"(n))

__device__ __forceinline__ void mma_tf32(float c[4],
        unsigned a0, unsigned a1, unsigned a2, unsigned a3,
        unsigned b0, unsigned b1){
    asm volatile("mma.sync.aligned.m16n8k8.row.col.f32.tf32.tf32.f32 "
        "{%0,%1,%2,%3},{%4,%5,%6,%7},{%8,%9},{%0,%1,%2,%3};\n"
        : "+f"(c[0]), "+f"(c[1]), "+f"(c[2]), "+f"(c[3])
        : "r"(a0), "r"(a1), "r"(a2), "r"(a3), "r"(b0), "r"(b1));
}

__device__ __forceinline__ float warpReduceSum(float v){
    #pragma unroll
    for (int o=16;o;o>>=1) v += __shfl_xor_sync(0xffffffffu, v, o);
    return v;
}
__device__ float blockReduceSum(float v){   // 256 threads
    __shared__ float s[8]; __shared__ float tot;
    int lane = threadIdx.x & 31, w = threadIdx.x >> 5;
    v = warpReduceSum(v);
    if (!lane) s[w] = v;
    __syncthreads();
    if (w == 0){
        float t = (lane < 8) ? s[lane] : 0.f;
        t = warpReduceSum(t);
        if (!lane) tot = t;
    }
    __syncthreads();
    return tot;
}

// ---------------- tf32 GEMM: C[M,N] = A[M,K] @ B[K,N] (+ Res) ----------------
// Tiles: BM=128, BN=128, BK=32; 8 warps of 32x64; cp.async double buffer.
// 2 CTAs per SM (smem 70KB, regs capped at 128) for latency hiding.
// doRope: apply RoPE to output pairs (used for Q/K projections) then tf32-round.
#define ASTR 36
#define ASZG (128*ASTR)          // 4608 floats per buffer
#define BSZG (32*136)            // 4352 floats per buffer
#define SMEM_N ((2*ASZG + 2*BSZG)*4)   // 71680 B

__global__ void __launch_bounds__(256, 2)
gemm_tf32(const float* __restrict__ A, int lda,
          const float* __restrict__ B, int ldb,
          float* __restrict__ C, int ldc,
          const float* __restrict__ Res,
          int K, int npm, int npn, int roundOut,
          const int* __restrict__ pos, int doRope)
{
    extern __shared__ float sm[];

    // grouped rasterization for L2 reuse
    int pid = blockIdx.x;
    const int GROUP = 8;
    int npg = GROUP * npn;
    int gid = pid / npg;
    int firstm = gid * GROUP;
    int gsz = min(GROUP, npm - firstm);
    int pm = firstm + (pid % npg) % gsz;
    int pn = (pid % npg) / gsz;
    int m0 = pm * 128, n0 = pn * 128;

    int KT = K / 32;
    int tid = threadIdx.x;
    int wid = tid >> 5, lane = tid & 31;
    int wm = (wid & 3) * 32;
    int wn = (wid >> 2) * 64;
    int rl = lane >> 2, l3 = lane & 3;

    auto loadA = [&](int buf, int kt){
        float* s = sm + buf * ASZG;
        int c = tid & 7;
        int r0 = tid >> 3;
        const float* gp = A + (long long)m0 * lda + kt * 32 + c * 4;
        #pragma unroll
        for (int w = 0; w < 4; w++){
            int row = r0 + 32 * w;
            cp16(smem_u32(s + row * ASTR + c * 4), gp + (long long)row * lda);
        }
    };
    auto loadB = [&](int buf, int kt){
        float* s = sm + 2 * ASZG + buf * BSZG;
        int c = tid & 31;
        int r0 = tid >> 5;
        const float* gp = B + (long long)(kt * 32) * ldb + n0 + c * 4;
        #pragma unroll
        for (int w = 0; w < 4; w++){
            int row = r0 + 8 * w;
            cp16(smem_u32(s + row * 136 + c * 4), gp + (long long)row * ldb);
        }
    };

    float acc[2][8][4];
    #pragma unroll
    for (int i=0;i<2;i++)
        #pragma unroll
        for (int j=0;j<8;j++)
            #pragma unroll
            for (int r=0;r<4;r++) acc[i][j][r] = 0.f;

    loadA(0, 0); loadB(0, 0); CP_COMMIT();

    for (int kt = 0; kt < KT; kt++){
        int buf = kt & 1;
        if (kt + 1 < KT){
            loadA(buf ^ 1, kt + 1); loadB(buf ^ 1, kt + 1);
            CP_COMMIT();
            CP_WAIT(1);
        } else {
            CP_WAIT(0);
        }
        __syncthreads();
        const float* sa = sm + buf * ASZG;
        const float* sb = sm + 2 * ASZG + buf * BSZG;

        #pragma unroll
        for (int ks = 0; ks < 4; ks++){
            int kk = ks * 8;
            unsigned a[2][4];
            #pragma unroll
            for (int mi = 0; mi < 2; mi++){
                const float* ap = sa + (wm + mi * 16 + rl) * ASTR + kk + l3;
                a[mi][0] = __float_as_uint(ap[0]);
                a[mi][1] = __float_as_uint(ap[8 * ASTR]);
                a[mi][2] = __float_as_uint(ap[4]);
                a[mi][3] = __float_as_uint(ap[8 * ASTR + 4]);
            }
            #pragma unroll
            for (int ni = 0; ni < 8; ni++){
                const float* bp = sb + (kk + l3) * 136 + wn + ni * 8 + rl;
                unsigned b0 = __float_as_uint(bp[0]);
                unsigned b1 = __float_as_uint(bp[4 * 136]);
                #pragma unroll
                for (int mi = 0; mi < 2; mi++)
                    mma_tf32(acc[mi][ni], a[mi][0], a[mi][1], a[mi][2], a[mi][3], b0, b1);
            }
        }
        __syncthreads();
    }

    // epilogue
    #pragma unroll
    for (int mi = 0; mi < 2; mi++){
        #pragma unroll
        for (int ni = 0; ni < 8; ni++){
            int row = m0 + wm + mi * 16 + rl;
            int col = n0 + wn + ni * 8 + l3 * 2;
            float v0 = acc[mi][ni][0];
            float v1 = acc[mi][ni][1];
            float v2 = acc[mi][ni][2];
            float v3 = acc[mi][ni][3];
            if (Res){
                float2 r01 = *(const float2*)(Res + (long long)row * ldc + col);
                float2 r23 = *(const float2*)(Res + (long long)(row + 8) * ldc + col);
                v0 += r01.x; v1 += r01.y; v2 += r23.x; v3 += r23.y;
            }
            if (doRope){
                int i = (col & 127) >> 1;
                float invf = g_invf[i];
                float a0 = (float)pos[row] * invf;
                float a1 = (float)pos[row + 8] * invf;
                float s0, c0, s1, c1;
                sincosf(a0, &s0, &c0);
                sincosf(a1, &s1, &c1);
                float t0 = v0 * c0 - v1 * s0;
                float t1 = v1 * c0 + v0 * s0;
                float t2 = v2 * c1 - v3 * s1;
                float t3 = v3 * c1 + v2 * s1;
                v0 = t0; v1 = t1; v2 = t2; v3 = t3;
            }
            if (roundOut | doRope){
                v0 = rna_tf32(v0); v1 = rna_tf32(v1);
                v2 = rna_tf32(v2); v3 = rna_tf32(v3);
            }
            *(float2*)(C + (long long)row * ldc + col)       = make_float2(v0, v1);
            *(float2*)(C + (long long)(row + 8) * ldc + col) = make_float2(v2, v3);
        }
    }
}

// ---------------- flash attention (gemm-style double buffer, 64-key tiles) ----
// Per CTA: one (b,h) and one 128-row q tile. 8 warps, each owns 16 q rows.
#define KSTR 140
#define VSTR 136
#define PSTR 76
#define KTILE 64
#define FLASH_SMEM ((2*KTILE*KSTR + 2*KTILE*VSTR + 8*16*PSTR)*4)   // 180224 B

__global__ void __launch_bounds__(256, 1)
flash_attn(const float* __restrict__ Q, const float* __restrict__ K,
           const float* __restrict__ V, float* __restrict__ O,
           float alpha)
{
    extern __shared__ float sm[];
    float* sKb = sm;                        // 2 * 64*140
    float* sVb = sm + 2*KTILE*KSTR;         // 2 * 64*136
    float* sP  = sVb + 2*KTILE*VSTR;        // 8*16*76

    int z = blockIdx.y;               // b*16+h
    int b = z >> 4, h = z & 15;
    int qt = (gridDim.x - 1) - blockIdx.x;   // heavy tiles first
    int q0 = qt * 128;
    const float* Qg = Q + ((long long)b * SEQ) * HIDDEN + h * HDIM;
    const float* Kg = K + ((long long)b * SEQ) * HIDDEN + h * HDIM;
    const float* Vg = V + ((long long)b * SEQ) * HIDDEN + h * HDIM;
    float* Og = O + ((long long)b * SEQ) * HIDDEN + h * HDIM;

    int tid = threadIdx.x, wid = tid >> 5, lane = tid & 31;
    int rl = lane >> 2, l3 = lane & 3;
    int qr = q0 + wid * 16;
    float* sPw = sP + wid * 16 * PSTR;

    // Q fragments in registers (already tf32-rounded + rope'd by producer)
    unsigned qf[16][4];
    #pragma unroll
    for (int ks = 0; ks < 16; ks++){
        const float* p0 = Qg + (long long)(qr + rl) * HIDDEN + ks * 8 + l3;
        const float* p1 = Qg + (long long)(qr + rl + 8) * HIDDEN + ks * 8 + l3;
        qf[ks][0] = __float_as_uint(p0[0]);
        qf[ks][1] = __float_as_uint(p1[0]);
        qf[ks][2] = __float_as_uint(p0[4]);
        qf[ks][3] = __float_as_uint(p1[4]);
    }

    float Oa[16][4];
    #pragma unroll
    for (int ni = 0; ni < 16; ni++){
        Oa[ni][0] = 0.f; Oa[ni][1] = 0.f; Oa[ni][2] = 0.f; Oa[ni][3] = 0.f;
    }
    float m0r = -1e30f, m1r = -1e30f, l0r = 0.f, l1r = 0.f;

    // one commit group per tile: K then V (64 rows x 128 floats each)
    auto loadKV = [&](int buf, int t){
        int c = tid & 31, r0 = tid >> 5;
        const float* kp = Kg + (long long)(t * KTILE) * HIDDEN + c * 4;
        const float* vp = Vg + (long long)(t * KTILE) * HIDDEN + c * 4;
        float* dk = sKb + buf * KTILE * KSTR;
        float* dv = sVb + buf * KTILE * VSTR;
        #pragma unroll
        for (int w = 0; w < 8; w++){
            int row = r0 + 8 * w;
            cp16(smem_u32(dk + row * KSTR + c * 4), kp + (long long)row * HIDDEN);
        }
        #pragma unroll
        for (int w = 0; w < 8; w++){
            int row = r0 + 8 * w;
            cp16(smem_u32(dv + row * VSTR + c * 4), vp + (long long)row * HIDDEN);
        }
    };

    int nt = 2 * qt + 2;
    loadKV(0, 0); CP_COMMIT();

    for (int t = 0; t < nt; t++){
        int buf = t & 1;
        if (t + 1 < nt){
            loadKV(buf ^ 1, t + 1);
            CP_COMMIT();
            CP_WAIT(1);
        } else {
            CP_WAIT(0);
        }
        __syncthreads();
        const float* cK = sKb + buf * KTILE * KSTR;
        const float* cV = sVb + buf * KTILE * VSTR;
        int diag = (t >= 2 * qt);
        int k0 = t * KTILE;

        // S = Q @ K^T over 64 keys
        float Sa[8][4];
        #pragma unroll
        for (int ni = 0; ni < 8; ni++){
            Sa[ni][0]=0.f; Sa[ni][1]=0.f; Sa[ni][2]=0.f; Sa[ni][3]=0.f;
        }
        #pragma unroll
        for (int ks = 0; ks < 16; ks++){
            #pragma unroll
            for (int ni = 0; ni < 8; ni++){
                int n = ni * 8 + rl;
                unsigned b0 = __float_as_uint(cK[n * KSTR + ks * 8 + l3]);
                unsigned b1 = __float_as_uint(cK[n * KSTR + ks * 8 + 4 + l3]);
                mma_tf32(Sa[ni], qf[ks][0], qf[ks][1], qf[ks][2], qf[ks][3], b0, b1);
            }
        }

        // scale + causal mask + row max
        int r0g = qr + rl, r1g = qr + rl + 8;
        float mx0 = -1e30f, mx1 = -1e30f;
        #pragma unroll
        for (int ni = 0; ni < 8; ni++){
            float x0 = Sa[ni][0] * alpha, x1 = Sa[ni][1] * alpha;
            float x2 = Sa[ni][2] * alpha, x3 = Sa[ni][3] * alpha;
            if (diag){
                int kg = k0 + ni * 8 + 2 * l3;
                if (kg     > r0g) x0 = -1e30f;
                if (kg + 1 > r0g) x1 = -1e30f;
                if (kg     > r1g) x2 = -1e30f;
                if (kg + 1 > r1g) x3 = -1e30f;
            }
            Sa[ni][0]=x0; Sa[ni][1]=x1; Sa[ni][2]=x2; Sa[ni][3]=x3;
            mx0 = fmaxf(mx0, fmaxf(x0, x1));
            mx1 = fmaxf(mx1, fmaxf(x2, x3));
        }
        mx0 = fmaxf(mx0, __shfl_xor_sync(0xffffffffu, mx0, 1));
        mx0 = fmaxf(mx0, __shfl_xor_sync(0xffffffffu, mx0, 2));
        mx1 = fmaxf(mx1, __shfl_xor_sync(0xffffffffu, mx1, 1));
        mx1 = fmaxf(mx1, __shfl_xor_sync(0xffffffffu, mx1, 2));

        float mn0 = fmaxf(m0r, mx0), mn1 = fmaxf(m1r, mx1);
        float cr0 = __expf(m0r - mn0), cr1 = __expf(m1r - mn1);
        m0r = mn0; m1r = mn1;
        l0r *= cr0; l1r *= cr1;
        #pragma unroll
        for (int ni = 0; ni < 16; ni++){
            Oa[ni][0] *= cr0; Oa[ni][1] *= cr0;
            Oa[ni][2] *= cr1; Oa[ni][3] *= cr1;
        }
        float rs0 = 0.f, rs1 = 0.f;
        #pragma unroll
        for (int ni = 0; ni < 8; ni++){
            float e0 = __expf(Sa[ni][0] - mn0);
            float e1 = __expf(Sa[ni][1] - mn0);
            float e2 = __expf(Sa[ni][2] - mn1);
            float e3 = __expf(Sa[ni][3] - mn1);
            rs0 += e0 + e1; rs1 += e2 + e3;
            int colp = ni * 8 + 2 * l3;
            *(float2*)(sPw + rl * PSTR + colp)       = make_float2(rna_tf32(e0), rna_tf32(e1));
            *(float2*)(sPw + (rl + 8) * PSTR + colp) = make_float2(rna_tf32(e2), rna_tf32(e3));
        }
        rs0 += __shfl_xor_sync(0xffffffffu, rs0, 1);
        rs0 += __shfl_xor_sync(0xffffffffu, rs0, 2);
        rs1 += __shfl_xor_sync(0xffffffffu, rs1, 1);
        rs1 += __shfl_xor_sync(0xffffffffu, rs1, 2);
        l0r += rs0; l1r += rs1;
        __syncwarp();

        // O += P @ V  (64 keys => ks 0..7)
        #pragma unroll
        for (int ks = 0; ks < 8; ks++){
            unsigned a0 = __float_as_uint(sPw[rl * PSTR + ks * 8 + l3]);
            unsigned a1 = __float_as_uint(sPw[(rl + 8) * PSTR + ks * 8 + l3]);
            unsigned a2 = __float_as_uint(sPw[rl * PSTR + ks * 8 + 4 + l3]);
            unsigned a3 = __float_as_uint(sPw[(rl + 8) * PSTR + ks * 8 + 4 + l3]);
            #pragma unroll
            for (int ni = 0; ni < 16; ni++){
                unsigned b0 = __float_as_uint(cV[(ks * 8 + l3) * VSTR + ni * 8 + rl]);
                unsigned b1 = __float_as_uint(cV[(ks * 8 + 4 + l3) * VSTR + ni * 8 + rl]);
                mma_tf32(Oa[ni], a0, a1, a2, a3, b0, b1);
            }
        }
        __syncthreads();   // all warps done with cK/cV before prefetch overwrites
    }

    // normalize + write (rounded: feeds WO gemm)
    float inv0 = 1.0f / l0r, inv1 = 1.0f / l1r;
    #pragma unroll
    for (int ni = 0; ni < 16; ni++){
        int col = ni * 8 + 2 * l3;
        *(float2*)(Og + (long long)(qr + rl) * HIDDEN + col) =
            make_float2(rna_tf32(Oa[ni][0] * inv0), rna_tf32(Oa[ni][1] * inv0));
        *(float2*)(Og + (long long)(qr + rl + 8) * HIDDEN + col) =
            make_float2(rna_tf32(Oa[ni][2] * inv1), rna_tf32(Oa[ni][3] * inv1));
    }
}

// ---------------- small kernels ----------------
__global__ void round_all(const float4* s0, float4* d0, const float4* s1, float4* d1,
                          const float4* s2, float4* d2, const float4* s3, float4* d3,
                          const float4* s4, float4* d4, const float4* s5, float4* d5,
                          const float4* s6, float4* d6)
{
    int gid = blockIdx.x * blockDim.x + threadIdx.x;
    int st = gridDim.x * blockDim.x;
    if (gid < 64) g_invf[gid] = (float)exp(-(double)gid * (log(500000.0) / 64.0));
    const int NA = HIDDEN * HIDDEN / 4;          // 1048576
    const int NB = HIDDEN * FFDIM / 4;           // 2883584
    const float4* srcs[7] = {s0, s1, s2, s3, s4, s5, s6};
    float4*       dsts[7] = {d0, d1, d2, d3, d4, d5, d6};
    #pragma unroll
    for (int seg = 0; seg < 7; seg++){
        int n = (seg < 4) ? NA : NB;
        const float4* s = srcs[seg];
        float4* d = dsts[seg];
        for (int i = gid; i < n; i += st){
            float4 v = s[i];
            v.x = rna_tf32(v.x); v.y = rna_tf32(v.y);
            v.z = rna_tf32(v.z); v.w = rna_tf32(v.w);
            d[i] = v;
        }
    }
}

__global__ void rmsnorm_kernel(const float* __restrict__ X, const float* __restrict__ sc,
                               float* __restrict__ O){
    long long base = (long long)blockIdx.x * HIDDEN;
    int tid = threadIdx.x;
    float v[8]; float ss = 0.f;
    #pragma unroll
    for (int i = 0; i < 8; i++){
        v[i] = X[base + tid + i * 256];
        ss += v[i] * v[i];
    }
    ss = blockReduceSum(ss);
    float r = rsqrtf(ss * (1.0f / (float)HIDDEN) + 1e-5f);
    #pragma unroll
    for (int i = 0; i < 8; i++){
        int c = tid + i * 256;
        O[base + c] = rna_tf32(v[i] * r * sc[c]);
    }
}

__global__ void silu_mul(float4* __restrict__ a, const float4* __restrict__ b, int n4){
    int i = blockIdx.x * blockDim.x + threadIdx.x;
    int st = gridDim.x * blockDim.x;
    for (; i < n4; i += st){
        float4 x = a[i], y = b[i];
        float s0 = x.x / (1.0f + expf(-x.x));
        float s1 = x.y / (1.0f + expf(-x.y));
        float s2 = x.z / (1.0f + expf(-x.z));
        float s3 = x.w / (1.0f + expf(-x.w));
        x.x = rna_tf32(s0 * y.x); x.y = rna_tf32(s1 * y.y);
        x.z = rna_tf32(s2 * y.z); x.w = rna_tf32(s3 * y.w);
        a[i] = x;
    }
}

// ---------------- launch ----------------
extern "C" void kernel_launch(void* const* d_in, const int* in_sizes, int n_in,
                              void* d_out, int out_size)
{
    const float* x   = (const float*)d_in[0];
    const int*   pos = (const int*)d_in[1];
    // d_in[2] = mask (causal; handled analytically)
    const float* wq  = (const float*)d_in[3];
    const float* wk  = (const float*)d_in[4];
    const float* wv  = (const float*)d_in[5];
    const float* wo  = (const float*)d_in[6];
    const float* asc = (const float*)d_in[7];
    const float* fsc = (const float*)d_in[8];
    const float* w1  = (const float*)d_in[9];
    const float* w3  = (const float*)d_in[10];
    const float* w2  = (const float*)d_in[11];
    float* out = (float*)d_out;

    float *p_xn,*p_q,*p_k,*p_v,*p_ao,*p_h,*p_ffn,*p_g1,*p_g3;
    float *p_wq,*p_wk,*p_wv,*p_wo,*p_w1,*p_w3,*p_w2;
    cudaGetSymbolAddress((void**)&p_xn, g_xnorm);
    cudaGetSymbolAddress((void**)&p_q,  g_q);
    cudaGetSymbolAddress((void**)&p_k,  g_k);
    cudaGetSymbolAddress((void**)&p_v,  g_v);
    cudaGetSymbolAddress((void**)&p_ao, g_attnout);
    cudaGetSymbolAddress((void**)&p_h,  g_h);
    cudaGetSymbolAddress((void**)&p_ffn,g_ffn);
    cudaGetSymbolAddress((void**)&p_g1, g_g1);
    cudaGetSymbolAddress((void**)&p_g3, g_g3);
    cudaGetSymbolAddress((void**)&p_wq, g_wq);
    cudaGetSymbolAddress((void**)&p_wk, g_wk);
    cudaGetSymbolAddress((void**)&p_wv, g_wv);
    cudaGetSymbolAddress((void**)&p_wo, g_wo);
    cudaGetSymbolAddress((void**)&p_w1, g_w1);
    cudaGetSymbolAddress((void**)&p_w3, g_w3);
    cudaGetSymbolAddress((void**)&p_w2, g_w2);

    cudaFuncSetAttribute(gemm_tf32, cudaFuncAttributeMaxDynamicSharedMemorySize, SMEM_N);
    cudaFuncSetAttribute(flash_attn, cudaFuncAttributeMaxDynamicSharedMemorySize, FLASH_SMEM);

    // 0. round weights to tf32 (rna) + inv_freq table
    round_all<<<4096,256>>>((const float4*)wq, (float4*)p_wq,
                            (const float4*)wk, (float4*)p_wk,
                            (const float4*)wv, (float4*)p_wv,
                            (const float4*)wo, (float4*)p_wo,
                            (const float4*)w1, (float4*)p_w1,
                            (const float4*)w3, (float4*)p_w3,
                            (const float4*)w2, (float4*)p_w2);

    // 1. rmsnorm (attn)
    rmsnorm_kernel<<<NTOK,256>>>(x, asc, p_xn);

    // 2-4. Q/K/V projections (rope fused into Q,K epilogues)
    dim3 gProj(32*16, 1, 1);
    gemm_tf32<<<gProj,256,SMEM_N>>>(p_xn,HIDDEN, p_wq,HIDDEN, p_q,HIDDEN,
                                    nullptr, HIDDEN, 32,16, 0, pos, 1);
    gemm_tf32<<<gProj,256,SMEM_N>>>(p_xn,HIDDEN, p_wk,HIDDEN, p_k,HIDDEN,
                                    nullptr, HIDDEN, 32,16, 0, pos, 1);
    gemm_tf32<<<gProj,256,SMEM_N>>>(p_xn,HIDDEN, p_wv,HIDDEN, p_v,HIDDEN,
                                    nullptr, HIDDEN, 32,16, 1, nullptr, 0);

    // 5. flash attention (profiled by ncu -s 5)
    flash_attn<<<dim3(16, BATCHN*NHEADS),256,FLASH_SMEM>>>(
        p_q, p_k, p_v, p_ao, 0.08838834764831845f);

    // 6. h = x + attn_out @ wo
    gemm_tf32<<<gProj,256,SMEM_N>>>(p_ao,HIDDEN, p_wo,HIDDEN, p_h,HIDDEN,
                                    x, HIDDEN, 32,16, 0, nullptr, 0);

    // 7. rmsnorm (ffn)
    rmsnorm_kernel<<<NTOK,256>>>(p_h, fsc, p_ffn);

    // 8-9. g1 = ff @ w1 ; g3 = ff @ w3
    dim3 gFF(32*44, 1, 1);
    gemm_tf32<<<gFF,256,SMEM_N>>>(p_ffn,HIDDEN, p_w1,FFDIM, p_g1,FFDIM,
                                  nullptr, HIDDEN, 32,44, 0, nullptr, 0);
    gemm_tf32<<<gFF,256,SMEM_N>>>(p_ffn,HIDDEN, p_w3,FFDIM, p_g3,FFDIM,
                                  nullptr, HIDDEN, 32,44, 0, nullptr, 0);

    // 10. g1 = silu(g1) * g3
    silu_mul<<<4096,256>>>((float4*)p_g1, (const float4*)p_g3, (int)((size_t)NTOK*FFDIM/4));

    // 11. out = h + g1 @ w2
    gemm_tf32<<<gProj,256,SMEM_N>>>(p_g1,FFDIM, p_w2,HIDDEN, out,HIDDEN,
                                    p_h, FFDIM, 32,16, 0, nullptr, 0);
}